// round 16
// baseline (speedup 1.0000x reference)
#include <cuda_runtime.h>
#include <cstdint>

// Shapes (fixed)
static constexpr int BATCH  = 16;
static constexpr int SEQ    = 1024;
static constexpr int H      = 256;
static constexpr int NHEADS = 8;
static constexpr int DH     = 32;
static constexpr int M      = BATCH * SEQ;   // 16384
static constexpr int F2     = 2 * H;         // 512

// Scratch. All MMA operands pre-rounded tf32. k-dims stored P8-interleaved.
__device__ float g_f  [M * F2];   // LN concat, cols P8-permuted
__device__ float g_q  [M * H];    // cols P8-permuted, pre-scaled by log2(e)/sqrt(dh)
__device__ float g_k  [M * H];    // cols P8-permuted
__device__ float g_v  [M * H];    // natural cols
__device__ float g_msg[M * H];    // cols P8-permuted (k-dim of Wo gemm)
__device__ float g_wq [F2 * H];   // transposed: [n][P8(k)]
__device__ float g_wk [F2 * H];
__device__ float g_wv [F2 * H];
__device__ float g_wo [H * H];

// ===========================================================================
// helpers
// ===========================================================================
__device__ __forceinline__ int P8(int j) { return ((j & 3) << 1) | ((j >> 2) & 1); }

__device__ __forceinline__ float to_tf32(float f) {
    uint32_t r;
    asm("cvt.rna.tf32.f32 %0, %1;" : "=r"(r) : "f"(f));
    return __uint_as_float(r);
}
__device__ __forceinline__ float ex2f(float x) {
    float r;
    asm("ex2.approx.f32 %0, %1;" : "=f"(r) : "f"(x));
    return r;
}
__device__ __forceinline__ uint32_t smem_u32(const void* p) {
    uint32_t a;
    asm("{ .reg .u64 t; cvta.to.shared.u64 t, %1; cvt.u32.u64 %0, t; }" : "=r"(a) : "l"(p));
    return a;
}
#define CP_ASYNC16(dst, src) \
    asm volatile("cp.async.cg.shared.global [%0], [%1], 16;" :: "r"(dst), "l"(src))
#define CP_COMMIT() asm volatile("cp.async.commit_group;" ::: "memory")
#define CP_WAIT(n)  asm volatile("cp.async.wait_group %0;" :: "n"(n) : "memory")

#define MMA_TF32(Cp, A0, A1, A2, A3, B0, B1)                                  \
    asm volatile("mma.sync.aligned.m16n8k8.row.col.f32.tf32.tf32.f32 "        \
        "{%0,%1,%2,%3},{%4,%5,%6,%7},{%8,%9},{%0,%1,%2,%3};"                  \
        : "+f"((Cp)[0]), "+f"((Cp)[1]), "+f"((Cp)[2]), "+f"((Cp)[3])          \
        : "r"(__float_as_uint(A0)), "r"(__float_as_uint(A1)),                 \
          "r"(__float_as_uint(A2)), "r"(__float_as_uint(A3)),                 \
          "r"(__float_as_uint(B0)), "r"(__float_as_uint(B1)))

__device__ __forceinline__ float warp_sum(float v) {
    #pragma unroll
    for (int o = 16; o; o >>= 1) v += __shfl_xor_sync(0xffffffffu, v, o);
    return v;
}

static constexpr float SC2 = 0.25507562f;   // log2(e)/sqrt(32)

// ===========================================================================
// K0: prep — transpose+P8-permute weights to tf32, zero outp.
// ===========================================================================
__global__ void __launch_bounds__(256) prep_kernel(
    const float* __restrict__ Wq, const float* __restrict__ Wk,
    const float* __restrict__ Wv, const float* __restrict__ Wo,
    float* __restrict__ outp)
{
    int t = blockIdx.x * 256 + threadIdx.x;
    if (t < M * 3) outp[t] = 0.f;
    const float* src; float* dst; int K2; int base;
    if (t < 16384)      { src = Wq; dst = g_wq; K2 = F2; base = t; }
    else if (t < 32768) { src = Wk; dst = g_wk; K2 = F2; base = t - 16384; }
    else if (t < 49152) { src = Wv; dst = g_wv; K2 = F2; base = t - 32768; }
    else                { src = Wo; dst = g_wo; K2 = H;  base = t - 49152; }
    int n = base & 255, kb = base >> 8;
    float v[8];
    #pragma unroll
    for (int j = 0; j < 8; j++)
        v[P8(j)] = to_tf32(src[(size_t)(kb * 8 + j) * H + n]);
    float4* d4 = (float4*)&dst[(size_t)n * K2 + kb * 8];
    d4[0] = make_float4(v[0], v[1], v[2], v[3]);
    d4[1] = make_float4(v[4], v[5], v[6], v[7]);
}

// ===========================================================================
// K1: dual LayerNorm + concat -> g_f (tf32, P8-permuted cols). Warp per row.
// ===========================================================================
__global__ void __launch_bounds__(256) ln_concat_kernel(
    const float* __restrict__ xs, const float* __restrict__ xo,
    const float* __restrict__ gs, const float* __restrict__ bs,
    const float* __restrict__ go, const float* __restrict__ bo)
{
    int w = threadIdx.x >> 5, lane = threadIdx.x & 31;
    int row = blockIdx.x * 8 + w;
    const float4* a4 = (const float4*)(xs + (size_t)row * H);
    const float4* c4 = (const float4*)(xo + (size_t)row * H);
    float4 a0 = a4[lane * 2], a1 = a4[lane * 2 + 1];
    float4 c0 = c4[lane * 2], c1 = c4[lane * 2 + 1];

    float sa  = a0.x + a0.y + a0.z + a0.w + a1.x + a1.y + a1.z + a1.w;
    float sa2 = a0.x*a0.x + a0.y*a0.y + a0.z*a0.z + a0.w*a0.w
              + a1.x*a1.x + a1.y*a1.y + a1.z*a1.z + a1.w*a1.w;
    float sc  = c0.x + c0.y + c0.z + c0.w + c1.x + c1.y + c1.z + c1.w;
    float sc2 = c0.x*c0.x + c0.y*c0.y + c0.z*c0.z + c0.w*c0.w
              + c1.x*c1.x + c1.y*c1.y + c1.z*c1.z + c1.w*c1.w;
    sa = warp_sum(sa); sa2 = warp_sum(sa2); sc = warp_sum(sc); sc2 = warp_sum(sc2);

    const float inv = 1.0f / (float)H;
    float ma = sa * inv, mc = sc * inv;
    float va = sa2 * inv - ma * ma;
    float vc = sc2 * inv - mc * mc;
    float ra = rsqrtf(va + 1e-5f), rc = rsqrtf(vc + 1e-5f);

    const float4* gs4 = (const float4*)gs; const float4* bs4 = (const float4*)bs;
    const float4* go4 = (const float4*)go; const float4* bo4 = (const float4*)bo;
    float4* f4 = (float4*)(g_f + (size_t)row * F2);

    float av[8] = {a0.x, a0.y, a0.z, a0.w, a1.x, a1.y, a1.z, a1.w};
    float cv[8] = {c0.x, c0.y, c0.z, c0.w, c1.x, c1.y, c1.z, c1.w};
    float4 g0 = gs4[lane * 2], g1 = gs4[lane * 2 + 1];
    float4 b0 = bs4[lane * 2], b1 = bs4[lane * 2 + 1];
    float4 h0 = go4[lane * 2], h1 = go4[lane * 2 + 1];
    float4 d0 = bo4[lane * 2], d1 = bo4[lane * 2 + 1];
    float gv[8] = {g0.x, g0.y, g0.z, g0.w, g1.x, g1.y, g1.z, g1.w};
    float bv[8] = {b0.x, b0.y, b0.z, b0.w, b1.x, b1.y, b1.z, b1.w};
    float hv[8] = {h0.x, h0.y, h0.z, h0.w, h1.x, h1.y, h1.z, h1.w};
    float dv[8] = {d0.x, d0.y, d0.z, d0.w, d1.x, d1.y, d1.z, d1.w};

    float oa[8], oc[8];
    #pragma unroll
    for (int j = 0; j < 8; j++) {
        oa[j] = to_tf32((av[j] - ma) * ra * gv[j] + bv[j]);
        oc[j] = to_tf32((cv[j] - mc) * rc * hv[j] + dv[j]);
    }
    f4[lane * 2]          = make_float4(oa[0], oa[4], oa[1], oa[5]);
    f4[lane * 2 + 1]      = make_float4(oa[2], oa[6], oa[3], oa[7]);
    f4[64 + lane * 2]     = make_float4(oc[0], oc[4], oc[1], oc[5]);
    f4[64 + lane * 2 + 1] = make_float4(oc[2], oc[6], oc[3], oc[7]);
}

// ===========================================================================
// K2: tf32 MMA GEMM (R14 exact — best known). Block 128x64, BK=32, 256 thr
// (8 warps 4m x 2n), cp.async double-buffered, LDS.64 fragments.
// which==0: A=g_f, z -> q/k/v (q pre-scaled by SC2; q,k P8 cols; v natural).
// which==3: A=g_msg, W=g_wo; fused epilogue: outx = xo + C, outp += C@Wp.
// ===========================================================================
__global__ void __launch_bounds__(256, 3) gemm_tf32_kernel(
    int which, const float* __restrict__ xo, const float* __restrict__ Wp,
    float* __restrict__ outx, float* __restrict__ outp)
{
    const float* A = (which == 0) ? g_f : g_msg;
    const int K = (which == 0) ? F2 : H;
    int z = blockIdx.z;
    const float* W = (which == 3) ? g_wo : ((z == 0) ? g_wq : (z == 1) ? g_wk : g_wv);

    __shared__ __align__(16) float As[2][128 * 40];   // [row][P8 k], stride 40
    __shared__ __align__(16) float Bs[2][64 * 40];    // [n][P8 k],  stride 40

    int tid = threadIdx.x, lane = tid & 31, wid = tid >> 5;
    int wm = wid & 3, wn = wid >> 2;
    int m0 = blockIdx.x * 128, n0 = blockIdx.y * 64;
    int g = lane >> 2, tc = lane & 3;

    int lrow = tid >> 3, lko = (tid & 7) * 4;

    uint32_t sA[2], sB[2];
    sA[0] = smem_u32(&As[0][0]); sA[1] = smem_u32(&As[1][0]);
    sB[0] = smem_u32(&Bs[0][0]); sB[1] = smem_u32(&Bs[1][0]);

    auto issue = [&](int ks) {
        int k0 = ks * 32, buf = ks & 1;
        #pragma unroll
        for (int i = 0; i < 4; i++) {
            int r = lrow + i * 32;
            CP_ASYNC16(sA[buf] + (r * 40 + lko) * 4, A + (size_t)(m0 + r) * K + k0 + lko);
        }
        #pragma unroll
        for (int i = 0; i < 2; i++) {
            int r = lrow + i * 32;
            CP_ASYNC16(sB[buf] + (r * 40 + lko) * 4, W + (size_t)(n0 + r) * K + k0 + lko);
        }
        CP_COMMIT();
    };

    float c[2][4][4] = {};
    issue(0);

    const int nk = K / 32;
    for (int ks = 0; ks < nk; ks++) {
        if (ks + 1 < nk) { issue(ks + 1); CP_WAIT(1); } else { CP_WAIT(0); }
        __syncthreads();
        const float* Ab = As[ks & 1];
        const float* Bb = Bs[ks & 1];
        #pragma unroll
        for (int kc = 0; kc < 4; kc++) {
            float2 alo[2], ahi[2];
            #pragma unroll
            for (int mf = 0; mf < 2; mf++) {
                int r0 = wm * 32 + mf * 16 + g;
                alo[mf] = *(const float2*)&Ab[r0 * 40 + kc * 8 + 2 * tc];
                ahi[mf] = *(const float2*)&Ab[(r0 + 8) * 40 + kc * 8 + 2 * tc];
            }
            #pragma unroll
            for (int nf = 0; nf < 4; nf++) {
                int nb = wn * 32 + nf * 8 + g;
                float2 bb = *(const float2*)&Bb[nb * 40 + kc * 8 + 2 * tc];
                MMA_TF32(c[0][nf], alo[0].x, ahi[0].x, alo[0].y, ahi[0].y, bb.x, bb.y);
                MMA_TF32(c[1][nf], alo[1].x, ahi[1].x, alo[1].y, ahi[1].y, bb.x, bb.y);
            }
        }
        __syncthreads();
    }

    if (which == 0) {
        if (z == 2) {   // v: natural layout
            #pragma unroll
            for (int mf = 0; mf < 2; mf++) {
                int row1 = m0 + wm * 32 + mf * 16 + g;
                #pragma unroll
                for (int nf = 0; nf < 4; nf++) {
                    int col = n0 + wn * 32 + nf * 8 + tc * 2;
                    *(float2*)&g_v[(size_t)row1 * H + col] =
                        make_float2(to_tf32(c[mf][nf][0]), to_tf32(c[mf][nf][1]));
                    *(float2*)&g_v[(size_t)(row1 + 8) * H + col] =
                        make_float2(to_tf32(c[mf][nf][2]), to_tf32(c[mf][nf][3]));
                }
            }
        } else {        // q/k: P8-permuted cols; q additionally scaled by SC2
            float* C = z ? g_k : g_q;
            float sc = z ? 1.0f : SC2;
            int p0 = (tc < 2) ? 4 * tc : 4 * (tc - 2) + 1;
            int p1 = p0 + 2;
            #pragma unroll
            for (int mf = 0; mf < 2; mf++) {
                int row1 = m0 + wm * 32 + mf * 16 + g;
                #pragma unroll
                for (int nf = 0; nf < 4; nf++) {
                    int base = n0 + wn * 32 + nf * 8;
                    C[(size_t)row1 * H + base + p0]       = to_tf32(c[mf][nf][0] * sc);
                    C[(size_t)row1 * H + base + p1]       = to_tf32(c[mf][nf][1] * sc);
                    C[(size_t)(row1 + 8) * H + base + p0] = to_tf32(c[mf][nf][2] * sc);
                    C[(size_t)(row1 + 8) * H + base + p1] = to_tf32(c[mf][nf][3] * sc);
                }
            }
        }
    } else {            // which==3: fused residual + position head
        float s[2][2][3] = {};
        #pragma unroll
        for (int mf = 0; mf < 2; mf++) {
            int rlo = m0 + wm * 32 + mf * 16 + g, rhi = rlo + 8;
            #pragma unroll
            for (int nf = 0; nf < 4; nf++) {
                int cb = n0 + wn * 32 + nf * 8 + tc * 2;
                float v0 = c[mf][nf][0], v1 = c[mf][nf][1];
                float v2 = c[mf][nf][2], v3 = c[mf][nf][3];
                const float* w0 = Wp + cb * 3;
                const float* w1 = Wp + (cb + 1) * 3;
                #pragma unroll
                for (int j = 0; j < 3; j++) {
                    s[mf][0][j] = fmaf(v0, w0[j], fmaf(v1, w1[j], s[mf][0][j]));
                    s[mf][1][j] = fmaf(v2, w0[j], fmaf(v3, w1[j], s[mf][1][j]));
                }
                *(float2*)&outx[(size_t)rlo * H + cb] =
                    make_float2(xo[(size_t)rlo * H + cb] + v0, xo[(size_t)rlo * H + cb + 1] + v1);
                *(float2*)&outx[(size_t)rhi * H + cb] =
                    make_float2(xo[(size_t)rhi * H + cb] + v2, xo[(size_t)rhi * H + cb + 1] + v3);
            }
        }
        #pragma unroll
        for (int mf = 0; mf < 2; mf++)
            #pragma unroll
            for (int hf = 0; hf < 2; hf++)
                #pragma unroll
                for (int j = 0; j < 3; j++) {
                    s[mf][hf][j] += __shfl_xor_sync(0xffffffffu, s[mf][hf][j], 1);
                    s[mf][hf][j] += __shfl_xor_sync(0xffffffffu, s[mf][hf][j], 2);
                }
        if (tc == 0) {
            #pragma unroll
            for (int mf = 0; mf < 2; mf++) {
                int rlo = m0 + wm * 32 + mf * 16 + g;
                #pragma unroll
                for (int j = 0; j < 3; j++) {
                    atomicAdd(&outp[rlo * 3 + j], s[mf][0][j]);
                    atomicAdd(&outp[(rlo + 8) * 3 + j], s[mf][1][j]);
                }
            }
        }
    }
}

// ===========================================================================
// K3: FA-style tf32 attention v9 — R14 body, but grid 512 (single wave:
// 512 <= 148*4 concurrent CTAs) with each CTA processing TWO tiles
// (bid, bid+512). Removes the 1.73-wave quantization tail.
// ===========================================================================
__global__ void __launch_bounds__(128, 4) attn_tf32_kernel() {
    __shared__ __align__(16) float Ks[2][64 * 40];
    __shared__ __align__(16) float Vs[2][64 * 40];

    int tid = threadIdx.x, lane = tid & 31, w = tid >> 5;
    int g = lane >> 2, tc = lane & 3;
    int lrow = tid >> 3, ls4 = (tid & 7) * 4;

    uint32_t sK[2], sV[2];
    sK[0] = smem_u32(&Ks[0][0]); sK[1] = smem_u32(&Ks[1][0]);
    sV[0] = smem_u32(&Vs[0][0]); sV[1] = smem_u32(&Vs[1][0]);

    int p0c = (tc < 2) ? 4 * tc : 4 * (tc - 2) + 1;
    int p1c = p0c + 2;
    const float one = 1.0f;
    const int NT = SEQ / 64;

    #pragma unroll 1
    for (int it = 0; it < 2; it++) {
        int tile = blockIdx.x + it * 512;          // 0..1023
        int qb = tile & 7;                         // SEQ/128 = 8
        int h  = (tile >> 3) & 7;
        int b  = tile >> 6;

        size_t rowbase = (size_t)b * SEQ;
        const float* Qg = g_q + (rowbase + qb * 128) * H + h * DH;
        const float* Kg = g_k + rowbase * H + h * DH;
        const float* Vg = g_v + rowbase * H + h * DH;

        auto issue = [&](int kt) {
            int buf = kt & 1;
            #pragma unroll
            for (int i = 0; i < 4; i++) {
                int lr = lrow + i * 16;
                int pr = (lr & ~7) | P8(lr & 7);   // K physical row placement
                size_t goff = (size_t)(kt * 64 + lr) * H + ls4;
                CP_ASYNC16(sK[buf] + (pr * 40 + ls4) * 4, Kg + goff);
                CP_ASYNC16(sV[buf] + (lr * 40 + ls4) * 4, Vg + goff);
            }
            CP_COMMIT();
        };
        issue(0);

        float qa[2][4][4];
        #pragma unroll
        for (int mf = 0; mf < 2; mf++) {
            const float* q0 = Qg + (size_t)(w * 32 + mf * 16 + g) * H;
            const float* q1 = q0 + 8 * H;
            #pragma unroll
            for (int kc = 0; kc < 4; kc++) {
                float2 ql = *(const float2*)&q0[kc * 8 + 2 * tc];
                float2 qh = *(const float2*)&q1[kc * 8 + 2 * tc];
                qa[mf][kc][0] = ql.x;
                qa[mf][kc][1] = qh.x;
                qa[mf][kc][2] = ql.y;
                qa[mf][kc][3] = qh.y;
            }
        }

        float of[2][4][4] = {};
        float lacc[2][4] = {};       // ones-MMA accumulator (all cols equal)

        for (int kt = 0; kt < NT; kt++) {
            if (kt + 1 < NT) { issue(kt + 1); CP_WAIT(1); } else { CP_WAIT(0); }
            __syncthreads();
            const float* Kb = Ks[kt & 1];
            const float* Vb = Vs[kt & 1];

            #pragma unroll
            for (int nf = 0; nf < 8; nf++) {
                float s0[4] = {}, s1[4] = {};
                #pragma unroll
                for (int kc = 0; kc < 4; kc++) {
                    float2 kb2 = *(const float2*)&Kb[(nf * 8 + g) * 40 + kc * 8 + 2 * tc];
                    MMA_TF32(s0, qa[0][kc][0], qa[0][kc][1], qa[0][kc][2], qa[0][kc][3], kb2.x, kb2.y);
                    MMA_TF32(s1, qa[1][kc][0], qa[1][kc][1], qa[1][kc][2], qa[1][kc][3], kb2.x, kb2.y);
                }
                float p0[4], p1[4];
                #pragma unroll
                for (int e = 0; e < 4; e++) { p0[e] = ex2f(s0[e]); p1[e] = ex2f(s1[e]); }

                // l += P @ 1 (same truncated P the PV MMAs see)
                MMA_TF32(lacc[0], p0[0], p0[2], p0[1], p0[3], one, one);
                MMA_TF32(lacc[1], p1[0], p1[2], p1[1], p1[3], one, one);

                #pragma unroll
                for (int nd = 0; nd < 4; nd++) {
                    float b0 = Vb[(nf * 8 + tc) * 40 + nd * 8 + g];
                    float b1 = Vb[(nf * 8 + tc + 4) * 40 + nd * 8 + g];
                    MMA_TF32(of[0][nd], p0[0], p0[2], p0[1], p0[3], b0, b1);
                    MMA_TF32(of[1][nd], p1[0], p1[2], p1[1], p1[3], b0, b1);
                }
            }
            __syncthreads();
        }

        #pragma unroll
        for (int mf = 0; mf < 2; mf++) {
            float inv1 = 1.0f / lacc[mf][0];   // row g sum (cols identical)
            float inv2 = 1.0f / lacc[mf][2];   // row g+8 sum
            float* Mg = g_msg + (rowbase + qb * 128 + w * 32 + mf * 16) * H + h * DH;
            #pragma unroll
            for (int nf = 0; nf < 4; nf++) {
                int base = nf * 8;
                Mg[(size_t)g * H + base + p0c]       = to_tf32(of[mf][nf][0] * inv1);
                Mg[(size_t)g * H + base + p1c]       = to_tf32(of[mf][nf][1] * inv1);
                Mg[(size_t)(g + 8) * H + base + p0c] = to_tf32(of[mf][nf][2] * inv2);
                Mg[(size_t)(g + 8) * H + base + p1c] = to_tf32(of[mf][nf][3] * inv2);
            }
        }
    }
}

// ===========================================================================
// Inputs: 0 x_source, 1 p_source(unused), 2 x_out, 3 p_out(unused),
// 4 g_s, 5 b_s, 6 g_o, 7 b_o, 8 Wq, 9 Wk, 10 Wv, 11 Wo, 12 Wp
// Output: x_out_new [16384*256] fp32, then p_out_new [16384*3] fp32.
// ===========================================================================
extern "C" void kernel_launch(void* const* d_in, const int* in_sizes, int n_in,
                              void* d_out, int out_size) {
    const float* xs = (const float*)d_in[0];
    const float* xo = (const float*)d_in[2];
    const float* gs = (const float*)d_in[4];
    const float* bs = (const float*)d_in[5];
    const float* go = (const float*)d_in[6];
    const float* bo = (const float*)d_in[7];
    const float* Wq = (const float*)d_in[8];
    const float* Wk = (const float*)d_in[9];
    const float* Wv = (const float*)d_in[10];
    const float* Wo = (const float*)d_in[11];
    const float* Wp = (const float*)d_in[12];
    float* outx = (float*)d_out;
    float* outp = (float*)d_out + (size_t)M * H;

    prep_kernel<<<224, 256>>>(Wq, Wk, Wv, Wo, outp);
    ln_concat_kernel<<<M / 8, 256>>>(xs, xo, gs, bs, go, bo);

    dim3 gq(M / 128, H / 64, 3);
    gemm_tf32_kernel<<<gq, 256>>>(0, nullptr, nullptr, nullptr, nullptr);

    attn_tf32_kernel<<<512, 128>>>();

    dim3 go_(M / 128, H / 64, 1);
    gemm_tf32_kernel<<<go_, 256>>>(3, xo, Wp, outx, outp);
}

// round 17
// speedup vs baseline: 1.1443x; 1.1443x over previous
#include <cuda_runtime.h>
#include <cstdint>

// Shapes (fixed)
static constexpr int BATCH  = 16;
static constexpr int SEQ    = 1024;
static constexpr int H      = 256;
static constexpr int NHEADS = 8;
static constexpr int DH     = 32;
static constexpr int M      = BATCH * SEQ;   // 16384
static constexpr int F2     = 2 * H;         // 512

// Scratch. All MMA operands pre-rounded tf32. k-dims stored P8-interleaved.
__device__ float g_f  [M * F2];   // LN concat, cols P8-permuted
__device__ float g_q  [M * H];    // cols P8-permuted, pre-scaled by log2(e)/sqrt(dh)
__device__ float g_k  [M * H];    // cols P8-permuted
__device__ float g_v  [M * H];    // natural cols
__device__ float g_msg[M * H];    // cols P8-permuted (k-dim of Wo gemm)
__device__ float g_wq [F2 * H];   // transposed: [n][P8(k)]
__device__ float g_wk [F2 * H];
__device__ float g_wv [F2 * H];
__device__ float g_wo [H * H];

// ===========================================================================
// helpers
// ===========================================================================
__device__ __forceinline__ int P8(int j) { return ((j & 3) << 1) | ((j >> 2) & 1); }

__device__ __forceinline__ float to_tf32(float f) {
    uint32_t r;
    asm("cvt.rna.tf32.f32 %0, %1;" : "=r"(r) : "f"(f));
    return __uint_as_float(r);
}
__device__ __forceinline__ float ex2f(float x) {
    float r;
    asm("ex2.approx.f32 %0, %1;" : "=f"(r) : "f"(x));
    return r;
}
__device__ __forceinline__ uint32_t smem_u32(const void* p) {
    uint32_t a;
    asm("{ .reg .u64 t; cvta.to.shared.u64 t, %1; cvt.u32.u64 %0, t; }" : "=r"(a) : "l"(p));
    return a;
}
#define CP_ASYNC16(dst, src) \
    asm volatile("cp.async.cg.shared.global [%0], [%1], 16;" :: "r"(dst), "l"(src))
#define CP_COMMIT() asm volatile("cp.async.commit_group;" ::: "memory")
#define CP_WAIT(n)  asm volatile("cp.async.wait_group %0;" :: "n"(n) : "memory")

#define MMA_TF32(Cp, A0, A1, A2, A3, B0, B1)                                  \
    asm volatile("mma.sync.aligned.m16n8k8.row.col.f32.tf32.tf32.f32 "        \
        "{%0,%1,%2,%3},{%4,%5,%6,%7},{%8,%9},{%0,%1,%2,%3};"                  \
        : "+f"((Cp)[0]), "+f"((Cp)[1]), "+f"((Cp)[2]), "+f"((Cp)[3])          \
        : "r"(__float_as_uint(A0)), "r"(__float_as_uint(A1)),                 \
          "r"(__float_as_uint(A2)), "r"(__float_as_uint(A3)),                 \
          "r"(__float_as_uint(B0)), "r"(__float_as_uint(B1)))

__device__ __forceinline__ float warp_sum(float v) {
    #pragma unroll
    for (int o = 16; o; o >>= 1) v += __shfl_xor_sync(0xffffffffu, v, o);
    return v;
}

static constexpr float SC2 = 0.25507562f;   // log2(e)/sqrt(32)

// ===========================================================================
// K1: fused [dual LayerNorm + concat] and [weight prep + outp zero].
// Blocks 0..2047: LN (warp per row). Blocks 2048..2271: prep (224 blocks).
// The two tasks are independent; fusing runs them concurrently.
// ===========================================================================
__global__ void __launch_bounds__(256) ln_prep_kernel(
    const float* __restrict__ xs, const float* __restrict__ xo,
    const float* __restrict__ gs, const float* __restrict__ bs,
    const float* __restrict__ go, const float* __restrict__ bo,
    const float* __restrict__ Wq, const float* __restrict__ Wk,
    const float* __restrict__ Wv, const float* __restrict__ Wo,
    float* __restrict__ outp)
{
    if (blockIdx.x >= 2048) {
        // ---- prep task ----
        int t = (blockIdx.x - 2048) * 256 + threadIdx.x;   // 0..57343
        if (t < M * 3) outp[t] = 0.f;
        const float* src; float* dst; int K2; int base;
        if (t < 16384)      { src = Wq; dst = g_wq; K2 = F2; base = t; }
        else if (t < 32768) { src = Wk; dst = g_wk; K2 = F2; base = t - 16384; }
        else if (t < 49152) { src = Wv; dst = g_wv; K2 = F2; base = t - 32768; }
        else                { src = Wo; dst = g_wo; K2 = H;  base = t - 49152; }
        int n = base & 255, kb = base >> 8;
        float v[8];
        #pragma unroll
        for (int j = 0; j < 8; j++)
            v[P8(j)] = to_tf32(src[(size_t)(kb * 8 + j) * H + n]);
        float4* d4 = (float4*)&dst[(size_t)n * K2 + kb * 8];
        d4[0] = make_float4(v[0], v[1], v[2], v[3]);
        d4[1] = make_float4(v[4], v[5], v[6], v[7]);
        return;
    }

    // ---- LN task ----
    int w = threadIdx.x >> 5, lane = threadIdx.x & 31;
    int row = blockIdx.x * 8 + w;
    const float4* a4 = (const float4*)(xs + (size_t)row * H);
    const float4* c4 = (const float4*)(xo + (size_t)row * H);
    float4 a0 = a4[lane * 2], a1 = a4[lane * 2 + 1];
    float4 c0 = c4[lane * 2], c1 = c4[lane * 2 + 1];

    float sa  = a0.x + a0.y + a0.z + a0.w + a1.x + a1.y + a1.z + a1.w;
    float sa2 = a0.x*a0.x + a0.y*a0.y + a0.z*a0.z + a0.w*a0.w
              + a1.x*a1.x + a1.y*a1.y + a1.z*a1.z + a1.w*a1.w;
    float sc  = c0.x + c0.y + c0.z + c0.w + c1.x + c1.y + c1.z + c1.w;
    float sc2 = c0.x*c0.x + c0.y*c0.y + c0.z*c0.z + c0.w*c0.w
              + c1.x*c1.x + c1.y*c1.y + c1.z*c1.z + c1.w*c1.w;
    sa = warp_sum(sa); sa2 = warp_sum(sa2); sc = warp_sum(sc); sc2 = warp_sum(sc2);

    const float inv = 1.0f / (float)H;
    float ma = sa * inv, mc = sc * inv;
    float va = sa2 * inv - ma * ma;
    float vc = sc2 * inv - mc * mc;
    float ra = rsqrtf(va + 1e-5f), rc = rsqrtf(vc + 1e-5f);

    const float4* gs4 = (const float4*)gs; const float4* bs4 = (const float4*)bs;
    const float4* go4 = (const float4*)go; const float4* bo4 = (const float4*)bo;
    float4* f4 = (float4*)(g_f + (size_t)row * F2);

    float av[8] = {a0.x, a0.y, a0.z, a0.w, a1.x, a1.y, a1.z, a1.w};
    float cv[8] = {c0.x, c0.y, c0.z, c0.w, c1.x, c1.y, c1.z, c1.w};
    float4 g0 = gs4[lane * 2], g1 = gs4[lane * 2 + 1];
    float4 b0 = bs4[lane * 2], b1 = bs4[lane * 2 + 1];
    float4 h0 = go4[lane * 2], h1 = go4[lane * 2 + 1];
    float4 d0 = bo4[lane * 2], d1 = bo4[lane * 2 + 1];
    float gv[8] = {g0.x, g0.y, g0.z, g0.w, g1.x, g1.y, g1.z, g1.w};
    float bv[8] = {b0.x, b0.y, b0.z, b0.w, b1.x, b1.y, b1.z, b1.w};
    float hv[8] = {h0.x, h0.y, h0.z, h0.w, h1.x, h1.y, h1.z, h1.w};
    float dv[8] = {d0.x, d0.y, d0.z, d0.w, d1.x, d1.y, d1.z, d1.w};

    float oa[8], oc[8];
    #pragma unroll
    for (int j = 0; j < 8; j++) {
        oa[j] = to_tf32((av[j] - ma) * ra * gv[j] + bv[j]);
        oc[j] = to_tf32((cv[j] - mc) * rc * hv[j] + dv[j]);
    }
    f4[lane * 2]          = make_float4(oa[0], oa[4], oa[1], oa[5]);
    f4[lane * 2 + 1]      = make_float4(oa[2], oa[6], oa[3], oa[7]);
    f4[64 + lane * 2]     = make_float4(oc[0], oc[4], oc[1], oc[5]);
    f4[64 + lane * 2 + 1] = make_float4(oc[2], oc[6], oc[3], oc[7]);
}

// ===========================================================================
// K2: tf32 MMA GEMM (R14 exact — best known). Block 128x64, BK=32, 256 thr
// (8 warps 4m x 2n), cp.async double-buffered, LDS.64 fragments.
// which==0: A=g_f, z -> q/k/v (q pre-scaled by SC2; q,k P8 cols; v natural).
// which==3: A=g_msg, W=g_wo; fused epilogue: outx = xo + C, outp += C@Wp.
// ===========================================================================
__global__ void __launch_bounds__(256, 3) gemm_tf32_kernel(
    int which, const float* __restrict__ xo, const float* __restrict__ Wp,
    float* __restrict__ outx, float* __restrict__ outp)
{
    const float* A = (which == 0) ? g_f : g_msg;
    const int K = (which == 0) ? F2 : H;
    int z = blockIdx.z;
    const float* W = (which == 3) ? g_wo : ((z == 0) ? g_wq : (z == 1) ? g_wk : g_wv);

    __shared__ __align__(16) float As[2][128 * 40];   // [row][P8 k], stride 40
    __shared__ __align__(16) float Bs[2][64 * 40];    // [n][P8 k],  stride 40

    int tid = threadIdx.x, lane = tid & 31, wid = tid >> 5;
    int wm = wid & 3, wn = wid >> 2;
    int m0 = blockIdx.x * 128, n0 = blockIdx.y * 64;
    int g = lane >> 2, tc = lane & 3;

    int lrow = tid >> 3, lko = (tid & 7) * 4;

    uint32_t sA[2], sB[2];
    sA[0] = smem_u32(&As[0][0]); sA[1] = smem_u32(&As[1][0]);
    sB[0] = smem_u32(&Bs[0][0]); sB[1] = smem_u32(&Bs[1][0]);

    auto issue = [&](int ks) {
        int k0 = ks * 32, buf = ks & 1;
        #pragma unroll
        for (int i = 0; i < 4; i++) {
            int r = lrow + i * 32;
            CP_ASYNC16(sA[buf] + (r * 40 + lko) * 4, A + (size_t)(m0 + r) * K + k0 + lko);
        }
        #pragma unroll
        for (int i = 0; i < 2; i++) {
            int r = lrow + i * 32;
            CP_ASYNC16(sB[buf] + (r * 40 + lko) * 4, W + (size_t)(n0 + r) * K + k0 + lko);
        }
        CP_COMMIT();
    };

    float c[2][4][4] = {};
    issue(0);

    const int nk = K / 32;
    for (int ks = 0; ks < nk; ks++) {
        if (ks + 1 < nk) { issue(ks + 1); CP_WAIT(1); } else { CP_WAIT(0); }
        __syncthreads();
        const float* Ab = As[ks & 1];
        const float* Bb = Bs[ks & 1];
        #pragma unroll
        for (int kc = 0; kc < 4; kc++) {
            float2 alo[2], ahi[2];
            #pragma unroll
            for (int mf = 0; mf < 2; mf++) {
                int r0 = wm * 32 + mf * 16 + g;
                alo[mf] = *(const float2*)&Ab[r0 * 40 + kc * 8 + 2 * tc];
                ahi[mf] = *(const float2*)&Ab[(r0 + 8) * 40 + kc * 8 + 2 * tc];
            }
            #pragma unroll
            for (int nf = 0; nf < 4; nf++) {
                int nb = wn * 32 + nf * 8 + g;
                float2 bb = *(const float2*)&Bb[nb * 40 + kc * 8 + 2 * tc];
                MMA_TF32(c[0][nf], alo[0].x, ahi[0].x, alo[0].y, ahi[0].y, bb.x, bb.y);
                MMA_TF32(c[1][nf], alo[1].x, ahi[1].x, alo[1].y, ahi[1].y, bb.x, bb.y);
            }
        }
        __syncthreads();
    }

    if (which == 0) {
        if (z == 2) {   // v: natural layout
            #pragma unroll
            for (int mf = 0; mf < 2; mf++) {
                int row1 = m0 + wm * 32 + mf * 16 + g;
                #pragma unroll
                for (int nf = 0; nf < 4; nf++) {
                    int col = n0 + wn * 32 + nf * 8 + tc * 2;
                    *(float2*)&g_v[(size_t)row1 * H + col] =
                        make_float2(to_tf32(c[mf][nf][0]), to_tf32(c[mf][nf][1]));
                    *(float2*)&g_v[(size_t)(row1 + 8) * H + col] =
                        make_float2(to_tf32(c[mf][nf][2]), to_tf32(c[mf][nf][3]));
                }
            }
        } else {        // q/k: P8-permuted cols; q additionally scaled by SC2
            float* C = z ? g_k : g_q;
            float sc = z ? 1.0f : SC2;
            int p0 = (tc < 2) ? 4 * tc : 4 * (tc - 2) + 1;
            int p1 = p0 + 2;
            #pragma unroll
            for (int mf = 0; mf < 2; mf++) {
                int row1 = m0 + wm * 32 + mf * 16 + g;
                #pragma unroll
                for (int nf = 0; nf < 4; nf++) {
                    int base = n0 + wn * 32 + nf * 8;
                    C[(size_t)row1 * H + base + p0]       = to_tf32(c[mf][nf][0] * sc);
                    C[(size_t)row1 * H + base + p1]       = to_tf32(c[mf][nf][1] * sc);
                    C[(size_t)(row1 + 8) * H + base + p0] = to_tf32(c[mf][nf][2] * sc);
                    C[(size_t)(row1 + 8) * H + base + p1] = to_tf32(c[mf][nf][3] * sc);
                }
            }
        }
    } else {            // which==3: fused residual + position head
        float s[2][2][3] = {};
        #pragma unroll
        for (int mf = 0; mf < 2; mf++) {
            int rlo = m0 + wm * 32 + mf * 16 + g, rhi = rlo + 8;
            #pragma unroll
            for (int nf = 0; nf < 4; nf++) {
                int cb = n0 + wn * 32 + nf * 8 + tc * 2;
                float v0 = c[mf][nf][0], v1 = c[mf][nf][1];
                float v2 = c[mf][nf][2], v3 = c[mf][nf][3];
                const float* w0 = Wp + cb * 3;
                const float* w1 = Wp + (cb + 1) * 3;
                #pragma unroll
                for (int j = 0; j < 3; j++) {
                    s[mf][0][j] = fmaf(v0, w0[j], fmaf(v1, w1[j], s[mf][0][j]));
                    s[mf][1][j] = fmaf(v2, w0[j], fmaf(v3, w1[j], s[mf][1][j]));
                }
                *(float2*)&outx[(size_t)rlo * H + cb] =
                    make_float2(xo[(size_t)rlo * H + cb] + v0, xo[(size_t)rlo * H + cb + 1] + v1);
                *(float2*)&outx[(size_t)rhi * H + cb] =
                    make_float2(xo[(size_t)rhi * H + cb] + v2, xo[(size_t)rhi * H + cb + 1] + v3);
            }
        }
        #pragma unroll
        for (int mf = 0; mf < 2; mf++)
            #pragma unroll
            for (int hf = 0; hf < 2; hf++)
                #pragma unroll
                for (int j = 0; j < 3; j++) {
                    s[mf][hf][j] += __shfl_xor_sync(0xffffffffu, s[mf][hf][j], 1);
                    s[mf][hf][j] += __shfl_xor_sync(0xffffffffu, s[mf][hf][j], 2);
                }
        if (tc == 0) {
            #pragma unroll
            for (int mf = 0; mf < 2; mf++) {
                int rlo = m0 + wm * 32 + mf * 16 + g;
                #pragma unroll
                for (int j = 0; j < 3; j++) {
                    atomicAdd(&outp[rlo * 3 + j], s[mf][0][j]);
                    atomicAdd(&outp[(rlo + 8) * 3 + j], s[mf][1][j]);
                }
            }
        }
    }
}

// ===========================================================================
// K3: FA-style tf32 attention (R14 exact — 92.3us, rel_err 4.74e-4).
// P fed unrounded to PV MMA; l via ones-MMA on the SAME truncated P so the
// truncation cancels in the softmax ratio.
// ===========================================================================
__global__ void __launch_bounds__(128, 4) attn_tf32_kernel() {
    __shared__ __align__(16) float Ks[2][64 * 40];
    __shared__ __align__(16) float Vs[2][64 * 40];

    int tid = threadIdx.x, lane = tid & 31, w = tid >> 5;
    int qb = blockIdx.x, h = blockIdx.y, b = blockIdx.z;
    int g = lane >> 2, tc = lane & 3;

    size_t rowbase = (size_t)b * SEQ;
    const float* Qg = g_q + (rowbase + qb * 128) * H + h * DH;
    const float* Kg = g_k + rowbase * H + h * DH;
    const float* Vg = g_v + rowbase * H + h * DH;

    uint32_t sK[2], sV[2];
    sK[0] = smem_u32(&Ks[0][0]); sK[1] = smem_u32(&Ks[1][0]);
    sV[0] = smem_u32(&Vs[0][0]); sV[1] = smem_u32(&Vs[1][0]);

    int lrow = tid >> 3, ls4 = (tid & 7) * 4;

    auto issue = [&](int kt) {
        int buf = kt & 1;
        #pragma unroll
        for (int i = 0; i < 4; i++) {
            int lr = lrow + i * 16;
            int pr = (lr & ~7) | P8(lr & 7);   // K physical row placement
            size_t goff = (size_t)(kt * 64 + lr) * H + ls4;
            CP_ASYNC16(sK[buf] + (pr * 40 + ls4) * 4, Kg + goff);
            CP_ASYNC16(sV[buf] + (lr * 40 + ls4) * 4, Vg + goff);
        }
        CP_COMMIT();
    };
    issue(0);

    float qa[2][4][4];
    #pragma unroll
    for (int mf = 0; mf < 2; mf++) {
        const float* q0 = Qg + (size_t)(w * 32 + mf * 16 + g) * H;
        const float* q1 = q0 + 8 * H;
        #pragma unroll
        for (int kc = 0; kc < 4; kc++) {
            float2 ql = *(const float2*)&q0[kc * 8 + 2 * tc];
            float2 qh = *(const float2*)&q1[kc * 8 + 2 * tc];
            qa[mf][kc][0] = ql.x;
            qa[mf][kc][1] = qh.x;
            qa[mf][kc][2] = ql.y;
            qa[mf][kc][3] = qh.y;
        }
    }

    float of[2][4][4] = {};
    float lacc[2][4] = {};           // ones-MMA accumulator (all cols equal)
    const float one = 1.0f;

    const int NT = SEQ / 64;
    for (int kt = 0; kt < NT; kt++) {
        if (kt + 1 < NT) { issue(kt + 1); CP_WAIT(1); } else { CP_WAIT(0); }
        __syncthreads();
        const float* Kb = Ks[kt & 1];
        const float* Vb = Vs[kt & 1];

        #pragma unroll
        for (int nf = 0; nf < 8; nf++) {
            float s0[4] = {}, s1[4] = {};
            #pragma unroll
            for (int kc = 0; kc < 4; kc++) {
                float2 kb2 = *(const float2*)&Kb[(nf * 8 + g) * 40 + kc * 8 + 2 * tc];
                MMA_TF32(s0, qa[0][kc][0], qa[0][kc][1], qa[0][kc][2], qa[0][kc][3], kb2.x, kb2.y);
                MMA_TF32(s1, qa[1][kc][0], qa[1][kc][1], qa[1][kc][2], qa[1][kc][3], kb2.x, kb2.y);
            }
            float p0[4], p1[4];
            #pragma unroll
            for (int e = 0; e < 4; e++) { p0[e] = ex2f(s0[e]); p1[e] = ex2f(s1[e]); }

            // l += P @ 1 (same truncated P the PV MMAs see)
            MMA_TF32(lacc[0], p0[0], p0[2], p0[1], p0[3], one, one);
            MMA_TF32(lacc[1], p1[0], p1[2], p1[1], p1[3], one, one);

            #pragma unroll
            for (int nd = 0; nd < 4; nd++) {
                float b0 = Vb[(nf * 8 + tc) * 40 + nd * 8 + g];
                float b1 = Vb[(nf * 8 + tc + 4) * 40 + nd * 8 + g];
                MMA_TF32(of[0][nd], p0[0], p0[2], p0[1], p0[3], b0, b1);
                MMA_TF32(of[1][nd], p1[0], p1[2], p1[1], p1[3], b0, b1);
            }
        }
        __syncthreads();
    }

    int p0c = (tc < 2) ? 4 * tc : 4 * (tc - 2) + 1;
    int p1c = p0c + 2;
    #pragma unroll
    for (int mf = 0; mf < 2; mf++) {
        float inv1 = 1.0f / lacc[mf][0];   // row g sum (cols identical)
        float inv2 = 1.0f / lacc[mf][2];   // row g+8 sum
        float* Mg = g_msg + (rowbase + qb * 128 + w * 32 + mf * 16) * H + h * DH;
        #pragma unroll
        for (int nf = 0; nf < 4; nf++) {
            int base = nf * 8;
            Mg[(size_t)g * H + base + p0c]       = to_tf32(of[mf][nf][0] * inv1);
            Mg[(size_t)g * H + base + p1c]       = to_tf32(of[mf][nf][1] * inv1);
            Mg[(size_t)(g + 8) * H + base + p0c] = to_tf32(of[mf][nf][2] * inv2);
            Mg[(size_t)(g + 8) * H + base + p1c] = to_tf32(of[mf][nf][3] * inv2);
        }
    }
}

// ===========================================================================
// Inputs: 0 x_source, 1 p_source(unused), 2 x_out, 3 p_out(unused),
// 4 g_s, 5 b_s, 6 g_o, 7 b_o, 8 Wq, 9 Wk, 10 Wv, 11 Wo, 12 Wp
// Output: x_out_new [16384*256] fp32, then p_out_new [16384*3] fp32.
// ===========================================================================
extern "C" void kernel_launch(void* const* d_in, const int* in_sizes, int n_in,
                              void* d_out, int out_size) {
    const float* xs = (const float*)d_in[0];
    const float* xo = (const float*)d_in[2];
    const float* gs = (const float*)d_in[4];
    const float* bs = (const float*)d_in[5];
    const float* go = (const float*)d_in[6];
    const float* bo = (const float*)d_in[7];
    const float* Wq = (const float*)d_in[8];
    const float* Wk = (const float*)d_in[9];
    const float* Wv = (const float*)d_in[10];
    const float* Wo = (const float*)d_in[11];
    const float* Wp = (const float*)d_in[12];
    float* outx = (float*)d_out;
    float* outp = (float*)d_out + (size_t)M * H;

    ln_prep_kernel<<<2048 + 224, 256>>>(xs, xo, gs, bs, go, bo, Wq, Wk, Wv, Wo, outp);

    dim3 gq(M / 128, H / 64, 3);
    gemm_tf32_kernel<<<gq, 256>>>(0, nullptr, nullptr, nullptr, nullptr);

    dim3 ga(SEQ / 128, NHEADS, BATCH);
    attn_tf32_kernel<<<ga, 128>>>();

    dim3 go_(M / 128, H / 64, 1);
    gemm_tf32_kernel<<<go_, 256>>>(3, xo, Wp, outx, outp);
}